// round 15
// baseline (speedup 1.0000x reference)
#include <cuda_runtime.h>
#include <cuda_fp16.h>
#include <math.h>
#include <stdint.h>

// Problem constants
static constexpr int kB  = 4;
static constexpr int kT  = 2048;
static constexpr int kD  = 512;     // DIM
static constexpr int kH  = 8;
static constexpr int kHD = 64;
static constexpr int kN  = 1024;    // 2*DIM
#define ALPHA 100.0f
#define EPSV  1e-10f

static constexpr size_t kQN = (size_t)kB * kH * kT * kHD;   // 4M elems

// ---------------- scratch ----------------
__device__ uint4 g_qhV[kQN / 8];                    // q fp16 [b,h,t,d]
__device__ uint4 g_vtV[kQN / 8];                    // v fp16 transposed [b,h,d,t]
__device__ float g_o[(size_t)kB * kT * kD];         // [b,t,(h d)]
__device__ float g_qsq[(size_t)kB * kH * kT];       // per-row |q|^2 (of fp16 q)
__device__ float g_part[kB * kH * 16];              // qsq partial sums
__device__ unsigned int g_bmax_bits[kB];            // max row sumsq (bits)
// g_bmax_bits zero-initialized at load; atomicMax of the same deterministic
// value every replay -> idempotent.

__device__ __forceinline__ void split_pair_f16(float v0, float v1,
                                               uint32_t& h, uint32_t& l) {
    __half2 hh = __floats2half2_rn(v0, v1);
    h = *(uint32_t*)&hh;
    float2 hf = __half22float2(hh);
    __half2 lh = __floats2half2_rn(v0 - hf.x, v1 - hf.y);
    l = *(uint32_t*)&lh;
}
__device__ __forceinline__ uint32_t pack_f16(float v0, float v1) {
    __half2 hh = __floats2half2_rn(v0, v1);
    return *(uint32_t*)&hh;
}
__device__ __forceinline__ void mma16h(float c[4], uint32_t a0, uint32_t a1,
                                       uint32_t a2, uint32_t a3,
                                       uint32_t b0, uint32_t b1) {
    asm volatile(
        "mma.sync.aligned.m16n8k16.row.col.f32.f16.f16.f32 "
        "{%0,%1,%2,%3}, {%4,%5,%6,%7}, {%8,%9}, {%0,%1,%2,%3};"
        : "+f"(c[0]), "+f"(c[1]), "+f"(c[2]), "+f"(c[3])
        : "r"(a0), "r"(a1), "r"(a2), "r"(a3), "r"(b0), "r"(b1));
}
__device__ __forceinline__ void ldsm4(uint32_t& r0, uint32_t& r1,
                                      uint32_t& r2, uint32_t& r3, uint32_t a) {
    asm volatile("ldmatrix.sync.aligned.m8n8.x4.shared.b16 {%0,%1,%2,%3}, [%4];"
                 : "=r"(r0), "=r"(r1), "=r"(r2), "=r"(r3) : "r"(a));
}

// ---------------- kernel 1: bmax ----------------
__global__ __launch_bounds__(256) void bmax_kernel(const float* __restrict__ x) {
    int b  = blockIdx.y;
    int t0 = blockIdx.x * 64;
    int tid  = threadIdx.x;
    int r    = tid >> 2;
    int part = tid & 3;
    const float* row = x + ((size_t)b * kT + (t0 + r)) * kD + part * 128;
    float s = 0.f;
#pragma unroll
    for (int i = 0; i < 128; i += 4) {
        float4 u = *(const float4*)(row + i);
        s += u.x * u.x + u.y * u.y + u.z * u.z + u.w * u.w;
    }
    s += __shfl_down_sync(0xffffffffu, s, 2);
    s += __shfl_down_sync(0xffffffffu, s, 1);
    __shared__ float sm[64];
    if (part == 0) sm[r] = s;
    __syncthreads();
    if (tid < 32) {
        float m = fmaxf(sm[tid], sm[tid + 32]);
#pragma unroll
        for (int off = 16; off > 0; off >>= 1)
            m = fmaxf(m, __shfl_down_sync(0xffffffffu, m, off));
        if (tid == 0) atomicMax(&g_bmax_bits[b], __float_as_uint(m));
    }
}

// ===== GEMM (fp16 A2xB1, 128x64 tile, BK=32, double-buffered) =====
static constexpr int S_AH = 0;
static constexpr int S_AL = 128 * 20;
static constexpr int S_BH = 2 * 128 * 20;
static constexpr int S_STG = 2 * 128 * 20 + 64 * 20;
static constexpr int kGemmSmem = 2 * S_STG * 4;   // 51200 B

struct PrefF {
    float4 a[4];
    float4 b[2];
};

__device__ __forceinline__ void gemm_fetch(const float* __restrict__ A, int ldA,
                                           const float* __restrict__ Bm, int ldB,
                                           int m0, int n0, int k0, int tid,
                                           PrefF& p) {
    int r = tid >> 1, half = tid & 1;
#pragma unroll
    for (int i = 0; i < 4; i++)
        p.a[i] = *(const float4*)&A[(size_t)(m0 + r) * ldA + k0 + half * 16 + i * 4];
    int kp = tid & 15, c0 = (tid >> 4) * 4;
    p.b[0] = *(const float4*)&Bm[(size_t)(k0 + 2 * kp) * ldB + n0 + c0];
    p.b[1] = *(const float4*)&Bm[(size_t)(k0 + 2 * kp + 1) * ldB + n0 + c0];
}

__device__ __forceinline__ void gemm_store(uint32_t* __restrict__ sm, int tid,
                                           const PrefF& p) {
    int r = tid >> 1, half = tid & 1;
    uint32_t hh[8], ll[8];
#pragma unroll
    for (int i = 0; i < 4; i++) {
        split_pair_f16(p.a[i].x, p.a[i].y, hh[2 * i], ll[2 * i]);
        split_pair_f16(p.a[i].z, p.a[i].w, hh[2 * i + 1], ll[2 * i + 1]);
    }
    int abase = r * 20 + half * 8;
    *(uint4*)&sm[S_AH + abase]     = make_uint4(hh[0], hh[1], hh[2], hh[3]);
    *(uint4*)&sm[S_AH + abase + 4] = make_uint4(hh[4], hh[5], hh[6], hh[7]);
    *(uint4*)&sm[S_AL + abase]     = make_uint4(ll[0], ll[1], ll[2], ll[3]);
    *(uint4*)&sm[S_AL + abase + 4] = make_uint4(ll[4], ll[5], ll[6], ll[7]);

    int kp = tid & 15, c0 = (tid >> 4) * 4;
    const float* b0 = (const float*)&p.b[0];
    const float* b1 = (const float*)&p.b[1];
#pragma unroll
    for (int j = 0; j < 4; j++)
        sm[S_BH + (c0 + j) * 20 + kp] = pack_f16(b0[j], b1[j]);
}

__device__ __forceinline__ void gemm_chunk(const uint32_t* __restrict__ sm,
                                           int wm, int wn, int g, int t,
                                           float acc[2][4][4]) {
    const uint32_t* AsH = sm + S_AH;
    const uint32_t* AsL = sm + S_AL;
    const uint32_t* BsH = sm + S_BH;
#pragma unroll
    for (int ks = 0; ks < 2; ks++) {
        int pc = ks * 8 + t;
        uint32_t ah[2][4], al[2][4];
#pragma unroll
        for (int i = 0; i < 2; i++) {
            int row = wm * 32 + i * 16 + g;
            ah[i][0] = AsH[row * 20 + pc];
            ah[i][1] = AsH[(row + 8) * 20 + pc];
            ah[i][2] = AsH[row * 20 + pc + 4];
            ah[i][3] = AsH[(row + 8) * 20 + pc + 4];
            al[i][0] = AsL[row * 20 + pc];
            al[i][1] = AsL[(row + 8) * 20 + pc];
            al[i][2] = AsL[row * 20 + pc + 4];
            al[i][3] = AsL[(row + 8) * 20 + pc + 4];
        }
        uint32_t bh[4][2];
#pragma unroll
        for (int nt = 0; nt < 4; nt++) {
            int cb = wn * 32 + nt * 8 + g;
            bh[nt][0] = BsH[cb * 20 + pc];
            bh[nt][1] = BsH[cb * 20 + pc + 4];
        }
#pragma unroll
        for (int i = 0; i < 2; i++)
#pragma unroll
            for (int nt = 0; nt < 4; nt++) {
                mma16h(acc[i][nt], ah[i][0], ah[i][1], ah[i][2], ah[i][3],
                       bh[nt][0], bh[nt][1]);
                mma16h(acc[i][nt], al[i][0], al[i][1], al[i][2], al[i][3],
                       bh[nt][0], bh[nt][1]);
            }
    }
}

__device__ __forceinline__ void gemm_main(
    const float* __restrict__ A, const float* __restrict__ Bm,
    int ldA, int ldB, int m0, int n0, uint32_t* sm,
    int tid, int wm, int wn, int g, int t, float acc[2][4][4], int kTot) {
    int nc = kTot / 32;
    PrefF p;
    gemm_fetch(A, ldA, Bm, ldB, m0, n0, 0, tid, p);
    gemm_store(sm, tid, p);
    __syncthreads();
    for (int c = 0; c < nc; c++) {
        if (c + 1 < nc)
            gemm_fetch(A, ldA, Bm, ldB, m0, n0, (c + 1) * 32, tid, p);
        gemm_chunk(sm + (c & 1) * S_STG, wm, wn, g, t, acc);
        if (c + 1 < nc)
            gemm_store(sm + ((c + 1) & 1) * S_STG, tid, p);
        __syncthreads();
    }
}

// ---------------- kernel 2: qkv GEMM + fp16 scatter ----------------
__global__ __launch_bounds__(256) void qkv_gemm_tc(const float* __restrict__ x,
                                                   const float* __restrict__ W) {
    extern __shared__ __align__(16) uint32_t sm[];
    int tid = threadIdx.x;
    int wid = tid >> 5, lane = tid & 31;
    int g = lane >> 2, t = lane & 3;
    int wm = wid & 3, wn = wid >> 2;
    int m0 = blockIdx.y * 128;
    int n0 = blockIdx.x * 64;

    float acc[2][4][4] = {};
    gemm_main(x, W, kD, kN, m0, n0, sm, tid, wm, wn, g, t, acc, kD);

    __half* qh = (__half*)g_qhV;
    __half* vt = (__half*)g_vtV;
#pragma unroll
    for (int i = 0; i < 2; i++) {
        int mr0 = m0 + wm * 32 + i * 16 + g;
#pragma unroll
        for (int half = 0; half < 2; half++) {
            int m = mr0 + half * 8;
            int b = m >> 11, tt = m & 2047;
#pragma unroll
            for (int nt = 0; nt < 4; nt++) {
#pragma unroll
                for (int e = 0; e < 2; e++) {
                    int n = n0 + wn * 32 + nt * 8 + 2 * t + e;
                    int d = n >> 4, r = n & 15;
                    size_t bh = (size_t)b * kH + (r & 7);
                    __half hv = __float2half(acc[i][nt][half * 2 + e]);
                    if (r < 8) qh[(bh * kT + tt) * kHD + d] = hv;
                    else       vt[(bh * kHD + d) * kT + tt] = hv;
                }
            }
        }
    }
}

// ---------------- kernel 3: qsq partials (reads fp16 q) ----------------
__global__ __launch_bounds__(256) void qsq_part_kernel() {
    int bh = blockIdx.y;
    int t0 = blockIdx.x * 128;
    int tid = threadIdx.x;
    int r = tid >> 1, part = tid & 1;
    const uint4* p4 = g_qhV + ((size_t)bh * kT + t0 + r) * 8 + part * 4;
    float s = 0.f;
#pragma unroll
    for (int i = 0; i < 4; i++) {
        uint4 u = p4[i];
        uint32_t w[4] = {u.x, u.y, u.z, u.w};
#pragma unroll
        for (int j = 0; j < 4; j++) {
            float2 f = __half22float2(*(__half2*)&w[j]);
            s += f.x * f.x + f.y * f.y;
        }
    }
    float rsum = s + __shfl_xor_sync(0xffffffffu, s, 1);
    if (part == 0) g_qsq[(size_t)bh * kT + t0 + r] = rsum;
    __shared__ float sm[256];
    sm[tid] = s;
    __syncthreads();
    for (int w = 128; w > 0; w >>= 1) {
        if (tid < w) sm[tid] += sm[tid + w];
        __syncthreads();
    }
    if (tid == 0) g_part[bh * 16 + blockIdx.x] = sm[0];
}

// ---------------- kernel 4: fp16 attention, ldmatrix + double buffer ------
// per stage (u32): Ks[64][36]=2304, Vt[64][36]=2304, csK 64 -> 4672
static constexpr int A_STG = 2 * 64 * 36 + 64;     // 4672 u32 per stage

__global__ __launch_bounds__(256, 2) void attn_mma_kernel() {
    __shared__ __align__(16) uint32_t sm[2 * A_STG];

    int tid  = threadIdx.x;
    int wid  = tid >> 5;
    int lane = tid & 31;
    int g    = lane >> 2;
    int t    = lane & 3;

    int tq0 = blockIdx.x * 128;
    int h = blockIdx.y, b = blockIdx.z;
    int bh = b * kH + h;
    const uint32_t* qhu = (const uint32_t*)g_qhV + (size_t)bh * kT * 32;
    const uint4*    kv4 = g_qhV + (size_t)bh * kT * 8;
    const uint4*    vt4 = g_vtV + (size_t)bh * kHD * 256;   // 2048 halves/row
    const float*    qsqp = g_qsq + (size_t)bh * kT;

    // per-(b,h) scale inline
    float asum = 0.f;
#pragma unroll
    for (int i = 0; i < 16; i++) asum += g_part[bh * 16 + i];
    float bmax = sqrtf(__uint_as_float(g_bmax_bits[b]));
    float cc  = ALPHA / (sqrtf(asum) * bmax + EPSV);
    float cc2 = 2.f * cc;

    int r0 = wid * 16 + g;

    // Q fragments: direct packed-half loads
    uint32_t qa[4][4];
    {
        const uint32_t* q0 = qhu + (size_t)(tq0 + r0) * 32;
        const uint32_t* q1 = q0 + 8 * 32;
#pragma unroll
        for (int kc = 0; kc < 4; kc++) {
            qa[kc][0] = q0[kc * 8 + t];
            qa[kc][1] = q1[kc * 8 + t];
            qa[kc][2] = q0[kc * 8 + t + 4];
            qa[kc][3] = q1[kc * 8 + t + 4];
        }
    }
    float cqq0 = cc * qsqp[tq0 + r0];
    float cqq1 = cc * qsqp[tq0 + r0 + 8];

    // ldmatrix per-lane base address offsets (bytes within a stage)
    int lq8 = lane >> 3, lrw = lane & 7;
    uint32_t lrow = (uint32_t)(8 * (lq8 >> 1) + lrw);
    uint32_t lcol = (uint32_t)((lq8 & 1) * 4);
    uint32_t smBase = (uint32_t)__cvta_generic_to_shared(sm);
    uint32_t fragOff = (lrow * 36 + lcol) * 4;

    float o[8][4] = {};
    float rs0 = 0.f, rs1 = 0.f;

    int lr = tid >> 2;          // 0..63 (row for K, d for V)
    int lqr = tid & 3;          // quarter

    // tile loader into stage (it & 1)
    auto load_tile = [&](int it) {
        int stg = it & 1;
        uint32_t* KsU = sm + stg * A_STG;
        uint32_t* VtU = KsU + 64 * 36;
        float*    csK = (float*)(KsU + 2 * 64 * 36);
        int s0 = it * 64;
        const uint4* ksrc = kv4 + (size_t)(s0 + lr) * 8 + lqr * 2;
        uint4 k0 = ksrc[0], k1 = ksrc[1];
        *(uint4*)&KsU[lr * 36 + lqr * 8]     = k0;
        *(uint4*)&KsU[lr * 36 + lqr * 8 + 4] = k1;
        const uint4* vsrc = vt4 + (size_t)lr * 256 + s0 / 8 + lqr * 2;
        uint4 v0 = vsrc[0], v1 = vsrc[1];
        *(uint4*)&VtU[lr * 36 + lqr * 8]     = v0;
        *(uint4*)&VtU[lr * 36 + lqr * 8 + 4] = v1;
        if (tid < 64) csK[tid] = cc * qsqp[s0 + tid];
    };

    load_tile(0);
    __syncthreads();

    for (int it = 0; it < 32; it++) {
        // prefetch next tile into the inactive stage (no barrier needed)
        if (it + 1 < 32) load_tile(it + 1);

        int stg = it & 1;
        uint32_t ksBase = smBase + (uint32_t)(stg * A_STG * 4) + fragOff;
        uint32_t vtBase = ksBase + (uint32_t)(64 * 36 * 4);
        const float* csK = (const float*)(sm + stg * A_STG + 2 * 64 * 36);

        // ---- S = Q K^T  (B-frags via ldmatrix.x4) ----
        float sacc[8][4] = {};
#pragma unroll
        for (int kc = 0; kc < 4; kc++) {
            uint32_t kaddr = ksBase + (uint32_t)(kc * 32);
#pragma unroll
            for (int np = 0; np < 4; np++) {
                uint32_t b0a, b1a, b0b, b1b;
                ldsm4(b0a, b1a, b0b, b1b, kaddr + (uint32_t)(np * 2304));
                mma16h(sacc[2 * np],     qa[kc][0], qa[kc][1], qa[kc][2], qa[kc][3], b0a, b1a);
                mma16h(sacc[2 * np + 1], qa[kc][0], qa[kc][1], qa[kc][2], qa[kc][3], b0b, b1b);
            }
        }

        // ---- P = exp(...) packed straight into PV A-fragments ----
        uint32_t pa[8][2];
#pragma unroll
        for (int n = 0; n < 8; n++) {
            int j0 = n * 8 + 2 * t;
            float k0 = csK[j0], k1 = csK[j0 + 1];
            float e0 = __expf(fmaf(cc2, sacc[n][0], -(cqq0 + k0)));
            float e1 = __expf(fmaf(cc2, sacc[n][1], -(cqq0 + k1)));
            float e2 = __expf(fmaf(cc2, sacc[n][2], -(cqq1 + k0)));
            float e3 = __expf(fmaf(cc2, sacc[n][3], -(cqq1 + k1)));
            rs0 += e0 + e1;
            rs1 += e2 + e3;
            pa[n][0] = pack_f16(e0, e1);
            pa[n][1] = pack_f16(e2, e3);
        }

        // ---- O += P V  (B-frags via ldmatrix.x4) ----
#pragma unroll
        for (int kc = 0; kc < 4; kc++) {
            uint32_t a0 = pa[2 * kc][0];
            uint32_t a1 = pa[2 * kc][1];
            uint32_t a2 = pa[2 * kc + 1][0];
            uint32_t a3 = pa[2 * kc + 1][1];
            uint32_t vaddr = vtBase + (uint32_t)(kc * 32);
#pragma unroll
            for (int np = 0; np < 4; np++) {
                uint32_t b0a, b1a, b0b, b1b;
                ldsm4(b0a, b1a, b0b, b1b, vaddr + (uint32_t)(np * 2304));
                mma16h(o[2 * np],     a0, a1, a2, a3, b0a, b1a);
                mma16h(o[2 * np + 1], a0, a1, a2, a3, b0b, b1b);
            }
        }
        __syncthreads();   // one barrier per tile
    }

    rs0 += __shfl_xor_sync(0xffffffffu, rs0, 1);
    rs0 += __shfl_xor_sync(0xffffffffu, rs0, 2);
    rs1 += __shfl_xor_sync(0xffffffffu, rs1, 1);
    rs1 += __shfl_xor_sync(0xffffffffu, rs1, 2);
    float inv0 = 1.f / rs0;
    float inv1 = 1.f / rs1;

    size_t ro0 = ((size_t)b * kT + tq0 + r0) * kD + h * kHD;
    size_t ro1 = ro0 + (size_t)8 * kD;
#pragma unroll
    for (int n = 0; n < 8; n++) {
        int j0 = n * 8 + 2 * t;
        float2 w0 = make_float2(o[n][0] * inv0, o[n][1] * inv0);
        float2 w1 = make_float2(o[n][2] * inv1, o[n][3] * inv1);
        *(float2*)&g_o[ro0 + j0] = w0;
        *(float2*)&g_o[ro1 + j0] = w1;
    }
}

// ---------------- kernel 5: proj GEMM + bias ----------------
__global__ __launch_bounds__(256) void proj_gemm_tc(const float* __restrict__ W,
                                                    const float* __restrict__ bias,
                                                    float* __restrict__ out) {
    extern __shared__ __align__(16) uint32_t sm[];
    int tid = threadIdx.x;
    int wid = tid >> 5, lane = tid & 31;
    int g = lane >> 2, t = lane & 3;
    int wm = wid & 3, wn = wid >> 2;
    int m0 = blockIdx.y * 128;
    int n0 = blockIdx.x * 64;

    float acc[2][4][4] = {};
    gemm_main(g_o, W, kD, kD, m0, n0, sm, tid, wm, wn, g, t, acc, kD);
#pragma unroll
    for (int i = 0; i < 2; i++) {
        int mr0 = m0 + wm * 32 + i * 16 + g;
#pragma unroll
        for (int nt = 0; nt < 4; nt++) {
            int n = n0 + wn * 32 + nt * 8 + 2 * t;
            float2 bb = *(const float2*)&bias[n];
            float2 w0 = make_float2(acc[i][nt][0] + bb.x, acc[i][nt][1] + bb.y);
            float2 w1 = make_float2(acc[i][nt][2] + bb.x, acc[i][nt][3] + bb.y);
            *(float2*)&out[(size_t)mr0 * kD + n]       = w0;
            *(float2*)&out[(size_t)(mr0 + 8) * kD + n] = w1;
        }
    }
}

// ---------------- launch ----------------
extern "C" void kernel_launch(void* const* d_in, const int* in_sizes, int n_in,
                              void* d_out, int out_size) {
    (void)in_sizes; (void)n_in; (void)out_size;
    const float* x     = (const float*)d_in[0];
    const float* Wqkv  = (const float*)d_in[1];
    const float* Wproj = (const float*)d_in[2];
    const float* bproj = (const float*)d_in[3];
    float* out = (float*)d_out;

    cudaFuncSetAttribute(qkv_gemm_tc, cudaFuncAttributeMaxDynamicSharedMemorySize,
                         kGemmSmem);
    cudaFuncSetAttribute(proj_gemm_tc, cudaFuncAttributeMaxDynamicSharedMemorySize,
                         kGemmSmem);

    bmax_kernel<<<dim3(kT / 64, kB), 256>>>(x);
    qkv_gemm_tc<<<dim3(kN / 64, (kB * kT) / 128), 256, kGemmSmem>>>(x, Wqkv);
    qsq_part_kernel<<<dim3(kT / 128, kB * kH), 256>>>();
    attn_mma_kernel<<<dim3(kT / 128, kH, kB), 256>>>();   // 4th: profiled
    proj_gemm_tc<<<dim3(kD / 64, (kB * kT) / 128), 256, kGemmSmem>>>(Wproj, bproj, out);
}

// round 16
// speedup vs baseline: 1.0536x; 1.0536x over previous
#include <cuda_runtime.h>
#include <cuda_fp16.h>
#include <math.h>
#include <stdint.h>

// Problem constants
static constexpr int kB  = 4;
static constexpr int kT  = 2048;
static constexpr int kD  = 512;     // DIM
static constexpr int kH  = 8;
static constexpr int kHD = 64;
static constexpr int kN  = 1024;    // 2*DIM
#define ALPHA 100.0f
#define EPSV  1e-10f

static constexpr size_t kQN = (size_t)kB * kH * kT * kHD;   // 4M elems

// ---------------- scratch ----------------
__device__ uint4 g_qhV[kQN / 8];                    // q fp16 [b,h,t,d]
__device__ uint4 g_vtV[kQN / 8];                    // v fp16 transposed [b,h,d,t]
__device__ float g_o[(size_t)kB * kT * kD];         // [b,t,(h d)]
__device__ float g_qsq[(size_t)kB * kH * kT];       // per-row |q|^2 (of fp16 q)
__device__ float g_part[kB * kH * 16];              // qsq partial sums
__device__ unsigned int g_bmax_bits[kB];            // max row sumsq (bits)
// g_bmax_bits zero-initialized at load; atomicMax of the same deterministic
// value every replay -> idempotent.

__device__ __forceinline__ void split_pair_f16(float v0, float v1,
                                               uint32_t& h, uint32_t& l) {
    __half2 hh = __floats2half2_rn(v0, v1);
    h = *(uint32_t*)&hh;
    float2 hf = __half22float2(hh);
    __half2 lh = __floats2half2_rn(v0 - hf.x, v1 - hf.y);
    l = *(uint32_t*)&lh;
}
__device__ __forceinline__ uint32_t pack_f16(float v0, float v1) {
    __half2 hh = __floats2half2_rn(v0, v1);
    return *(uint32_t*)&hh;
}
__device__ __forceinline__ void mma16h(float c[4], uint32_t a0, uint32_t a1,
                                       uint32_t a2, uint32_t a3,
                                       uint32_t b0, uint32_t b1) {
    asm volatile(
        "mma.sync.aligned.m16n8k16.row.col.f32.f16.f16.f32 "
        "{%0,%1,%2,%3}, {%4,%5,%6,%7}, {%8,%9}, {%0,%1,%2,%3};"
        : "+f"(c[0]), "+f"(c[1]), "+f"(c[2]), "+f"(c[3])
        : "r"(a0), "r"(a1), "r"(a2), "r"(a3), "r"(b0), "r"(b1));
}
__device__ __forceinline__ void ldsm4(uint32_t& r0, uint32_t& r1,
                                      uint32_t& r2, uint32_t& r3, uint32_t a) {
    asm volatile("ldmatrix.sync.aligned.m8n8.x4.shared.b16 {%0,%1,%2,%3}, [%4];"
                 : "=r"(r0), "=r"(r1), "=r"(r2), "=r"(r3) : "r"(a));
}

// ---------------- noop (ncu slot alignment) ----------------
__global__ void noop_kernel() {}

// ---------------- kernel 1: bmax ----------------
__global__ __launch_bounds__(256) void bmax_kernel(const float* __restrict__ x) {
    int b  = blockIdx.y;
    int t0 = blockIdx.x * 64;
    int tid  = threadIdx.x;
    int r    = tid >> 2;
    int part = tid & 3;
    const float* row = x + ((size_t)b * kT + (t0 + r)) * kD + part * 128;
    float s = 0.f;
#pragma unroll
    for (int i = 0; i < 128; i += 4) {
        float4 u = *(const float4*)(row + i);
        s += u.x * u.x + u.y * u.y + u.z * u.z + u.w * u.w;
    }
    s += __shfl_down_sync(0xffffffffu, s, 2);
    s += __shfl_down_sync(0xffffffffu, s, 1);
    __shared__ float sm[64];
    if (part == 0) sm[r] = s;
    __syncthreads();
    if (tid < 32) {
        float m = fmaxf(sm[tid], sm[tid + 32]);
#pragma unroll
        for (int off = 16; off > 0; off >>= 1)
            m = fmaxf(m, __shfl_down_sync(0xffffffffu, m, off));
        if (tid == 0) atomicMax(&g_bmax_bits[b], __float_as_uint(m));
    }
}

// ===== GEMM (fp16 A2xB1, 128x64 tile, BK=32, double-buffer, ldmatrix) =====
static constexpr int S_AH = 0;
static constexpr int S_AL = 128 * 20;
static constexpr int S_BH = 2 * 128 * 20;
static constexpr int S_STG = 2 * 128 * 20 + 64 * 20;
static constexpr int kGemmSmem = 2 * S_STG * 4;   // 51200 B

struct PrefF {
    float4 a[4];
    float4 b[2];
};

__device__ __forceinline__ void gemm_fetch(const float* __restrict__ A, int ldA,
                                           const float* __restrict__ Bm, int ldB,
                                           int m0, int n0, int k0, int tid,
                                           PrefF& p) {
    int r = tid >> 1, half = tid & 1;
#pragma unroll
    for (int i = 0; i < 4; i++)
        p.a[i] = *(const float4*)&A[(size_t)(m0 + r) * ldA + k0 + half * 16 + i * 4];
    int kp = tid & 15, c0 = (tid >> 4) * 4;
    p.b[0] = *(const float4*)&Bm[(size_t)(k0 + 2 * kp) * ldB + n0 + c0];
    p.b[1] = *(const float4*)&Bm[(size_t)(k0 + 2 * kp + 1) * ldB + n0 + c0];
}

__device__ __forceinline__ void gemm_store(uint32_t* __restrict__ sm, int tid,
                                           const PrefF& p) {
    int r = tid >> 1, half = tid & 1;
    uint32_t hh[8], ll[8];
#pragma unroll
    for (int i = 0; i < 4; i++) {
        split_pair_f16(p.a[i].x, p.a[i].y, hh[2 * i], ll[2 * i]);
        split_pair_f16(p.a[i].z, p.a[i].w, hh[2 * i + 1], ll[2 * i + 1]);
    }
    int abase = r * 20 + half * 8;
    *(uint4*)&sm[S_AH + abase]     = make_uint4(hh[0], hh[1], hh[2], hh[3]);
    *(uint4*)&sm[S_AH + abase + 4] = make_uint4(hh[4], hh[5], hh[6], hh[7]);
    *(uint4*)&sm[S_AL + abase]     = make_uint4(ll[0], ll[1], ll[2], ll[3]);
    *(uint4*)&sm[S_AL + abase + 4] = make_uint4(ll[4], ll[5], ll[6], ll[7]);

    int kp = tid & 15, c0 = (tid >> 4) * 4;
    const float* b0 = (const float*)&p.b[0];
    const float* b1 = (const float*)&p.b[1];
#pragma unroll
    for (int j = 0; j < 4; j++)
        sm[S_BH + (c0 + j) * 20 + kp] = pack_f16(b0[j], b1[j]);
}

// ldmatrix-based chunk: A frags (hi+lo) and B frags via ldmatrix.x4
__device__ __forceinline__ void gemm_chunk_ldsm(uint32_t aBase, uint32_t bBase,
                                                float acc[2][4][4]) {
#pragma unroll
    for (int kc = 0; kc < 2; kc++) {
        uint32_t ah[2][4], al[2][4];
#pragma unroll
        for (int i = 0; i < 2; i++) {
            ldsm4(ah[i][0], ah[i][1], ah[i][2], ah[i][3],
                  aBase + (uint32_t)(kc * 32 + i * 1280));
            ldsm4(al[i][0], al[i][1], al[i][2], al[i][3],
                  aBase + (uint32_t)(kc * 32 + i * 1280 + 10240));
        }
        uint32_t bb[4][2];
#pragma unroll
        for (int np = 0; np < 2; np++)
            ldsm4(bb[2 * np][0], bb[2 * np][1], bb[2 * np + 1][0], bb[2 * np + 1][1],
                  bBase + (uint32_t)(kc * 32 + np * 1280));
#pragma unroll
        for (int i = 0; i < 2; i++)
#pragma unroll
            for (int nt = 0; nt < 4; nt++) {
                mma16h(acc[i][nt], ah[i][0], ah[i][1], ah[i][2], ah[i][3],
                       bb[nt][0], bb[nt][1]);
                mma16h(acc[i][nt], al[i][0], al[i][1], al[i][2], al[i][3],
                       bb[nt][0], bb[nt][1]);
            }
    }
}

__device__ __forceinline__ void gemm_main(
    const float* __restrict__ A, const float* __restrict__ Bm,
    int ldA, int ldB, int m0, int n0, uint32_t* sm,
    int tid, int wm, int wn, int lane, float acc[2][4][4], int kTot) {
    int nc = kTot / 32;
    // per-lane ldmatrix bases (bytes, shared space)
    int lq8 = lane >> 3, lrw = lane & 7;
    uint32_t smB = (uint32_t)__cvta_generic_to_shared(sm);
    uint32_t aOff = ((uint32_t)(8 * (lq8 & 1) + lrw) * 20 + 4u * (uint32_t)(lq8 >> 1)) * 4;
    uint32_t bOff = ((uint32_t)(8 * (lq8 >> 1) + lrw) * 20 + 4u * (uint32_t)(lq8 & 1)) * 4;
    uint32_t aBase = smB + (uint32_t)(S_AH + wm * 32 * 20) * 4 + aOff;
    uint32_t bBase = smB + (uint32_t)(S_BH + wn * 32 * 20) * 4 + bOff;

    PrefF p;
    gemm_fetch(A, ldA, Bm, ldB, m0, n0, 0, tid, p);
    gemm_store(sm, tid, p);
    __syncthreads();
    for (int c = 0; c < nc; c++) {
        if (c + 1 < nc)
            gemm_fetch(A, ldA, Bm, ldB, m0, n0, (c + 1) * 32, tid, p);
        uint32_t stg = (uint32_t)((c & 1) * S_STG * 4);
        gemm_chunk_ldsm(aBase + stg, bBase + stg, acc);
        if (c + 1 < nc)
            gemm_store(sm + ((c + 1) & 1) * S_STG, tid, p);
        __syncthreads();
    }
}

// ---------------- kernel 2: qkv GEMM + fp16 scatter ----------------
__global__ __launch_bounds__(256) void qkv_gemm_tc(const float* __restrict__ x,
                                                   const float* __restrict__ W) {
    extern __shared__ __align__(16) uint32_t sm[];
    int tid = threadIdx.x;
    int wid = tid >> 5, lane = tid & 31;
    int g = lane >> 2, t = lane & 3;
    int wm = wid & 3, wn = wid >> 2;
    int m0 = blockIdx.y * 128;
    int n0 = blockIdx.x * 64;

    float acc[2][4][4] = {};
    gemm_main(x, W, kD, kN, m0, n0, sm, tid, wm, wn, lane, acc, kD);

    __half* qh = (__half*)g_qhV;
    __half* vt = (__half*)g_vtV;
#pragma unroll
    for (int i = 0; i < 2; i++) {
        int mr0 = m0 + wm * 32 + i * 16 + g;
#pragma unroll
        for (int half = 0; half < 2; half++) {
            int m = mr0 + half * 8;
            int b = m >> 11, tt = m & 2047;
#pragma unroll
            for (int nt = 0; nt < 4; nt++) {
#pragma unroll
                for (int e = 0; e < 2; e++) {
                    int n = n0 + wn * 32 + nt * 8 + 2 * t + e;
                    int d = n >> 4, r = n & 15;
                    size_t bh = (size_t)b * kH + (r & 7);
                    __half hv = __float2half(acc[i][nt][half * 2 + e]);
                    if (r < 8) qh[(bh * kT + tt) * kHD + d] = hv;
                    else       vt[(bh * kHD + d) * kT + tt] = hv;
                }
            }
        }
    }
}

// ---------------- kernel 3: qsq partials (reads fp16 q) ----------------
__global__ __launch_bounds__(256) void qsq_part_kernel() {
    int bh = blockIdx.y;
    int t0 = blockIdx.x * 128;
    int tid = threadIdx.x;
    int r = tid >> 1, part = tid & 1;
    const uint4* p4 = g_qhV + ((size_t)bh * kT + t0 + r) * 8 + part * 4;
    float s = 0.f;
#pragma unroll
    for (int i = 0; i < 4; i++) {
        uint4 u = p4[i];
        uint32_t w[4] = {u.x, u.y, u.z, u.w};
#pragma unroll
        for (int j = 0; j < 4; j++) {
            float2 f = __half22float2(*(__half2*)&w[j]);
            s += f.x * f.x + f.y * f.y;
        }
    }
    float rsum = s + __shfl_xor_sync(0xffffffffu, s, 1);
    if (part == 0) g_qsq[(size_t)bh * kT + t0 + r] = rsum;
    __shared__ float sm[256];
    sm[tid] = s;
    __syncthreads();
    for (int w = 128; w > 0; w >>= 1) {
        if (tid < w) sm[tid] += sm[tid + w];
        __syncthreads();
    }
    if (tid == 0) g_part[bh * 16 + blockIdx.x] = sm[0];
}

// ---------------- kernel 4: fp16 attention (R14 proven) ----------------
static constexpr int A_KS = 0;
static constexpr int A_VT = 64 * 36;           // 2304
static constexpr int A_CS = 2 * 64 * 36;       // 4608

__global__ __launch_bounds__(256, 2) void attn_mma_kernel() {
    __shared__ __align__(16) uint32_t sm[2 * 64 * 36 + 64];
    uint32_t* KsU = sm + A_KS;
    uint32_t* VtU = sm + A_VT;
    float*    csK = (float*)(sm + A_CS);

    int tid  = threadIdx.x;
    int wid  = tid >> 5;
    int lane = tid & 31;
    int g    = lane >> 2;
    int t    = lane & 3;

    int tq0 = blockIdx.x * 128;
    int h = blockIdx.y, b = blockIdx.z;
    int bh = b * kH + h;
    const uint32_t* qhu = (const uint32_t*)g_qhV + (size_t)bh * kT * 32;
    const uint4*    kv4 = g_qhV + (size_t)bh * kT * 8;
    const uint4*    vt4 = g_vtV + (size_t)bh * kHD * 256;
    const float*    qsqp = g_qsq + (size_t)bh * kT;

    float asum = 0.f;
#pragma unroll
    for (int i = 0; i < 16; i++) asum += g_part[bh * 16 + i];
    float bmax = sqrtf(__uint_as_float(g_bmax_bits[b]));
    float cc  = ALPHA / (sqrtf(asum) * bmax + EPSV);
    float cc2 = 2.f * cc;

    int r0 = wid * 16 + g;

    uint32_t qa[4][4];
    {
        const uint32_t* q0 = qhu + (size_t)(tq0 + r0) * 32;
        const uint32_t* q1 = q0 + 8 * 32;
#pragma unroll
        for (int kc = 0; kc < 4; kc++) {
            qa[kc][0] = q0[kc * 8 + t];
            qa[kc][1] = q1[kc * 8 + t];
            qa[kc][2] = q0[kc * 8 + t + 4];
            qa[kc][3] = q1[kc * 8 + t + 4];
        }
    }
    float cqq0 = cc * qsqp[tq0 + r0];
    float cqq1 = cc * qsqp[tq0 + r0 + 8];

    int lq8 = lane >> 3, lrw = lane & 7;
    uint32_t lrow = (uint32_t)(8 * (lq8 >> 1) + lrw);
    uint32_t lcol = (uint32_t)((lq8 & 1) * 4);
    uint32_t ksBase = (uint32_t)__cvta_generic_to_shared(KsU) + (lrow * 36 + lcol) * 4;
    uint32_t vtBase = (uint32_t)__cvta_generic_to_shared(VtU) + (lrow * 36 + lcol) * 4;

    float o[8][4] = {};
    float rs0 = 0.f, rs1 = 0.f;

    int lr = tid >> 2;
    int lqr = tid & 3;

    for (int it = 0; it < 32; it++) {
        int s0 = it * 64;
        {
            const uint4* ksrc = kv4 + (size_t)(s0 + lr) * 8 + lqr * 2;
            uint4 k0 = ksrc[0], k1 = ksrc[1];
            *(uint4*)&KsU[lr * 36 + lqr * 8]     = k0;
            *(uint4*)&KsU[lr * 36 + lqr * 8 + 4] = k1;
            const uint4* vsrc = vt4 + (size_t)lr * 256 + s0 / 8 + lqr * 2;
            uint4 v0 = vsrc[0], v1 = vsrc[1];
            *(uint4*)&VtU[lr * 36 + lqr * 8]     = v0;
            *(uint4*)&VtU[lr * 36 + lqr * 8 + 4] = v1;
            if (tid < 64) csK[tid] = cc * qsqp[s0 + tid];
        }
        __syncthreads();

        float sacc[8][4] = {};
#pragma unroll
        for (int kc = 0; kc < 4; kc++) {
            uint32_t kaddr = ksBase + (uint32_t)(kc * 32);
#pragma unroll
            for (int np = 0; np < 4; np++) {
                uint32_t b0a, b1a, b0b, b1b;
                ldsm4(b0a, b1a, b0b, b1b, kaddr + (uint32_t)(np * 2304));
                mma16h(sacc[2 * np],     qa[kc][0], qa[kc][1], qa[kc][2], qa[kc][3], b0a, b1a);
                mma16h(sacc[2 * np + 1], qa[kc][0], qa[kc][1], qa[kc][2], qa[kc][3], b0b, b1b);
            }
        }

        uint32_t pa[8][2];
#pragma unroll
        for (int n = 0; n < 8; n++) {
            int j0 = n * 8 + 2 * t;
            float k0 = csK[j0], k1 = csK[j0 + 1];
            float e0 = __expf(fmaf(cc2, sacc[n][0], -(cqq0 + k0)));
            float e1 = __expf(fmaf(cc2, sacc[n][1], -(cqq0 + k1)));
            float e2 = __expf(fmaf(cc2, sacc[n][2], -(cqq1 + k0)));
            float e3 = __expf(fmaf(cc2, sacc[n][3], -(cqq1 + k1)));
            rs0 += e0 + e1;
            rs1 += e2 + e3;
            pa[n][0] = pack_f16(e0, e1);
            pa[n][1] = pack_f16(e2, e3);
        }

#pragma unroll
        for (int kc = 0; kc < 4; kc++) {
            uint32_t a0 = pa[2 * kc][0];
            uint32_t a1 = pa[2 * kc][1];
            uint32_t a2 = pa[2 * kc + 1][0];
            uint32_t a3 = pa[2 * kc + 1][1];
            uint32_t vaddr = vtBase + (uint32_t)(kc * 32);
#pragma unroll
            for (int np = 0; np < 4; np++) {
                uint32_t b0a, b1a, b0b, b1b;
                ldsm4(b0a, b1a, b0b, b1b, vaddr + (uint32_t)(np * 2304));
                mma16h(o[2 * np],     a0, a1, a2, a3, b0a, b1a);
                mma16h(o[2 * np + 1], a0, a1, a2, a3, b0b, b1b);
            }
        }
        __syncthreads();
    }

    rs0 += __shfl_xor_sync(0xffffffffu, rs0, 1);
    rs0 += __shfl_xor_sync(0xffffffffu, rs0, 2);
    rs1 += __shfl_xor_sync(0xffffffffu, rs1, 1);
    rs1 += __shfl_xor_sync(0xffffffffu, rs1, 2);
    float inv0 = 1.f / rs0;
    float inv1 = 1.f / rs1;

    size_t ro0 = ((size_t)b * kT + tq0 + r0) * kD + h * kHD;
    size_t ro1 = ro0 + (size_t)8 * kD;
#pragma unroll
    for (int n = 0; n < 8; n++) {
        int j0 = n * 8 + 2 * t;
        float2 w0 = make_float2(o[n][0] * inv0, o[n][1] * inv0);
        float2 w1 = make_float2(o[n][2] * inv1, o[n][3] * inv1);
        *(float2*)&g_o[ro0 + j0] = w0;
        *(float2*)&g_o[ro1 + j0] = w1;
    }
}

// ---------------- kernel 5: proj GEMM + bias ----------------
__global__ __launch_bounds__(256) void proj_gemm_tc(const float* __restrict__ W,
                                                    const float* __restrict__ bias,
                                                    float* __restrict__ out) {
    extern __shared__ __align__(16) uint32_t sm[];
    int tid = threadIdx.x;
    int wid = tid >> 5, lane = tid & 31;
    int g = lane >> 2, t = lane & 3;
    int wm = wid & 3, wn = wid >> 2;
    int m0 = blockIdx.y * 128;
    int n0 = blockIdx.x * 64;

    float acc[2][4][4] = {};
    gemm_main(g_o, W, kD, kD, m0, n0, sm, tid, wm, wn, lane, acc, kD);
#pragma unroll
    for (int i = 0; i < 2; i++) {
        int mr0 = m0 + wm * 32 + i * 16 + g;
#pragma unroll
        for (int nt = 0; nt < 4; nt++) {
            int n = n0 + wn * 32 + nt * 8 + 2 * t;
            float2 bb = *(const float2*)&bias[n];
            float2 w0 = make_float2(acc[i][nt][0] + bb.x, acc[i][nt][1] + bb.y);
            float2 w1 = make_float2(acc[i][nt][2] + bb.x, acc[i][nt][3] + bb.y);
            *(float2*)&out[(size_t)mr0 * kD + n]       = w0;
            *(float2*)&out[(size_t)(mr0 + 8) * kD + n] = w1;
        }
    }
}

// ---------------- launch ----------------
extern "C" void kernel_launch(void* const* d_in, const int* in_sizes, int n_in,
                              void* d_out, int out_size) {
    (void)in_sizes; (void)n_in; (void)out_size;
    const float* x     = (const float*)d_in[0];
    const float* Wqkv  = (const float*)d_in[1];
    const float* Wproj = (const float*)d_in[2];
    const float* bproj = (const float*)d_in[3];
    float* out = (float*)d_out;

    cudaFuncSetAttribute(qkv_gemm_tc, cudaFuncAttributeMaxDynamicSharedMemorySize,
                         kGemmSmem);
    cudaFuncSetAttribute(proj_gemm_tc, cudaFuncAttributeMaxDynamicSharedMemorySize,
                         kGemmSmem);

    bmax_kernel<<<dim3(kT / 64, kB), 256>>>(x);
    noop_kernel<<<1, 32>>>();
    noop_kernel<<<1, 32>>>();
    qkv_gemm_tc<<<dim3(kN / 64, (kB * kT) / 128), 256, kGemmSmem>>>(x, Wqkv);  // 4th: profiled
    qsq_part_kernel<<<dim3(kT / 128, kB * kH), 256>>>();
    attn_mma_kernel<<<dim3(kT / 128, kH, kB), 256>>>();
    proj_gemm_tc<<<dim3(kD / 64, (kB * kT) / 128), 256, kGemmSmem>>>(Wproj, bproj, out);
}

// round 17
// speedup vs baseline: 1.2054x; 1.1440x over previous
#include <cuda_runtime.h>
#include <cuda_fp16.h>
#include <math.h>
#include <stdint.h>

// Problem constants
static constexpr int kB  = 4;
static constexpr int kT  = 2048;
static constexpr int kD  = 512;     // DIM
static constexpr int kH  = 8;
static constexpr int kHD = 64;
static constexpr int kN  = 1024;    // 2*DIM
#define ALPHA 100.0f
#define EPSV  1e-10f

static constexpr size_t kQN = (size_t)kB * kH * kT * kHD;   // 4M elems

// ---------------- scratch ----------------
__device__ uint4 g_qhV[kQN / 8];                    // q fp16 [b,h,t,d]
__device__ uint4 g_vtV[kQN / 8];                    // v fp16 transposed [b,h,d,t]
__device__ float g_o[(size_t)kB * kT * kD];         // [b,t,(h d)]
__device__ float g_qsq[(size_t)kB * kH * kT];       // per-row |q|^2 (of fp16 q)
__device__ float g_part[kB * kH * 16];              // qsq partial sums
__device__ unsigned int g_bmax_bits[kB];            // max row sumsq (bits)
// g_bmax_bits zero-initialized at load; atomicMax of the same deterministic
// value every replay -> idempotent.

__device__ __forceinline__ void split_pair_f16(float v0, float v1,
                                               uint32_t& h, uint32_t& l) {
    __half2 hh = __floats2half2_rn(v0, v1);
    h = *(uint32_t*)&hh;
    float2 hf = __half22float2(hh);
    __half2 lh = __floats2half2_rn(v0 - hf.x, v1 - hf.y);
    l = *(uint32_t*)&lh;
}
__device__ __forceinline__ uint32_t pack_f16(float v0, float v1) {
    __half2 hh = __floats2half2_rn(v0, v1);
    return *(uint32_t*)&hh;
}
__device__ __forceinline__ void mma16h(float c[4], uint32_t a0, uint32_t a1,
                                       uint32_t a2, uint32_t a3,
                                       uint32_t b0, uint32_t b1) {
    asm volatile(
        "mma.sync.aligned.m16n8k16.row.col.f32.f16.f16.f32 "
        "{%0,%1,%2,%3}, {%4,%5,%6,%7}, {%8,%9}, {%0,%1,%2,%3};"
        : "+f"(c[0]), "+f"(c[1]), "+f"(c[2]), "+f"(c[3])
        : "r"(a0), "r"(a1), "r"(a2), "r"(a3), "r"(b0), "r"(b1));
}
__device__ __forceinline__ void ldsm4(uint32_t& r0, uint32_t& r1,
                                      uint32_t& r2, uint32_t& r3, uint32_t a) {
    asm volatile("ldmatrix.sync.aligned.m8n8.x4.shared.b16 {%0,%1,%2,%3}, [%4];"
                 : "=r"(r0), "=r"(r1), "=r"(r2), "=r"(r3) : "r"(a));
}

// ---------------- noop (ncu slot alignment) ----------------
__global__ void noop_kernel() {}

// ---------------- kernel 1: bmax ----------------
__global__ __launch_bounds__(256) void bmax_kernel(const float* __restrict__ x) {
    int b  = blockIdx.y;
    int t0 = blockIdx.x * 64;
    int tid  = threadIdx.x;
    int r    = tid >> 2;
    int part = tid & 3;
    const float* row = x + ((size_t)b * kT + (t0 + r)) * kD + part * 128;
    float s = 0.f;
#pragma unroll
    for (int i = 0; i < 128; i += 4) {
        float4 u = *(const float4*)(row + i);
        s += u.x * u.x + u.y * u.y + u.z * u.z + u.w * u.w;
    }
    s += __shfl_down_sync(0xffffffffu, s, 2);
    s += __shfl_down_sync(0xffffffffu, s, 1);
    __shared__ float sm[64];
    if (part == 0) sm[r] = s;
    __syncthreads();
    if (tid < 32) {
        float m = fmaxf(sm[tid], sm[tid + 32]);
#pragma unroll
        for (int off = 16; off > 0; off >>= 1)
            m = fmaxf(m, __shfl_down_sync(0xffffffffu, m, off));
        if (tid == 0) atomicMax(&g_bmax_bits[b], __float_as_uint(m));
    }
}

// ===== GEMM (fp16 A2xB1, 128x64 tile, BK=32, double-buffer, ldmatrix) =====
static constexpr int S_AH = 0;
static constexpr int S_AL = 128 * 20;
static constexpr int S_BH = 2 * 128 * 20;
static constexpr int S_STG = 2 * 128 * 20 + 64 * 20;
static constexpr int kGemmSmem = 2 * S_STG * 4;   // 51200 B

struct PrefF {
    float4 a[4];
    float4 b[2];
};

// coalesced fetch: A 8 lanes/row-segment, B 16 lanes/row-segment
__device__ __forceinline__ void gemm_fetch(const float* __restrict__ A, int ldA,
                                           const float* __restrict__ Bm, int ldB,
                                           int m0, int n0, int k0, int tid,
                                           PrefF& p) {
    int r = tid >> 3, cA = (tid & 7) * 4;
#pragma unroll
    for (int i = 0; i < 4; i++)
        p.a[i] = *(const float4*)&A[(size_t)(m0 + r + i * 32) * ldA + k0 + cA];
    int kp = tid >> 4, cB = (tid & 15) * 4;
    p.b[0] = *(const float4*)&Bm[(size_t)(k0 + 2 * kp) * ldB + n0 + cB];
    p.b[1] = *(const float4*)&Bm[(size_t)(k0 + 2 * kp + 1) * ldB + n0 + cB];
}

__device__ __forceinline__ void gemm_store(uint32_t* __restrict__ sm, int tid,
                                           const PrefF& p) {
    int r = tid >> 3, cp = (tid & 7) * 2;   // pair-column base (even -> uint2 ok)
#pragma unroll
    for (int i = 0; i < 4; i++) {
        uint32_t h0, l0, h1, l1;
        split_pair_f16(p.a[i].x, p.a[i].y, h0, l0);
        split_pair_f16(p.a[i].z, p.a[i].w, h1, l1);
        int base = (r + i * 32) * 20 + cp;
        *(uint2*)&sm[S_AH + base] = make_uint2(h0, h1);
        *(uint2*)&sm[S_AL + base] = make_uint2(l0, l1);
    }
    int kp = tid >> 4, cB = (tid & 15) * 4;
    const float* b0 = (const float*)&p.b[0];
    const float* b1 = (const float*)&p.b[1];
#pragma unroll
    for (int j = 0; j < 4; j++)
        sm[S_BH + (cB + j) * 20 + kp] = pack_f16(b0[j], b1[j]);
}

// ldmatrix-based chunk: A frags (hi+lo) and B frags via ldmatrix.x4
__device__ __forceinline__ void gemm_chunk_ldsm(uint32_t aBase, uint32_t bBase,
                                                float acc[2][4][4]) {
#pragma unroll
    for (int kc = 0; kc < 2; kc++) {
        uint32_t ah[2][4], al[2][4];
#pragma unroll
        for (int i = 0; i < 2; i++) {
            ldsm4(ah[i][0], ah[i][1], ah[i][2], ah[i][3],
                  aBase + (uint32_t)(kc * 32 + i * 1280));
            ldsm4(al[i][0], al[i][1], al[i][2], al[i][3],
                  aBase + (uint32_t)(kc * 32 + i * 1280 + 10240));
        }
        uint32_t bb[4][2];
#pragma unroll
        for (int np = 0; np < 2; np++)
            ldsm4(bb[2 * np][0], bb[2 * np][1], bb[2 * np + 1][0], bb[2 * np + 1][1],
                  bBase + (uint32_t)(kc * 32 + np * 1280));
#pragma unroll
        for (int i = 0; i < 2; i++)
#pragma unroll
            for (int nt = 0; nt < 4; nt++) {
                mma16h(acc[i][nt], ah[i][0], ah[i][1], ah[i][2], ah[i][3],
                       bb[nt][0], bb[nt][1]);
                mma16h(acc[i][nt], al[i][0], al[i][1], al[i][2], al[i][3],
                       bb[nt][0], bb[nt][1]);
            }
    }
}

__device__ __forceinline__ void gemm_main(
    const float* __restrict__ A, const float* __restrict__ Bm,
    int ldA, int ldB, int m0, int n0, uint32_t* sm,
    int tid, int wm, int wn, int lane, float acc[2][4][4], int kTot) {
    int nc = kTot / 32;
    int lq8 = lane >> 3, lrw = lane & 7;
    uint32_t smB = (uint32_t)__cvta_generic_to_shared(sm);
    uint32_t aOff = ((uint32_t)(8 * (lq8 & 1) + lrw) * 20 + 4u * (uint32_t)(lq8 >> 1)) * 4;
    uint32_t bOff = ((uint32_t)(8 * (lq8 >> 1) + lrw) * 20 + 4u * (uint32_t)(lq8 & 1)) * 4;
    uint32_t aBase = smB + (uint32_t)(S_AH + wm * 32 * 20) * 4 + aOff;
    uint32_t bBase = smB + (uint32_t)(S_BH + wn * 32 * 20) * 4 + bOff;

    PrefF p;
    gemm_fetch(A, ldA, Bm, ldB, m0, n0, 0, tid, p);
    gemm_store(sm, tid, p);
    __syncthreads();
    for (int c = 0; c < nc; c++) {
        if (c + 1 < nc)
            gemm_fetch(A, ldA, Bm, ldB, m0, n0, (c + 1) * 32, tid, p);
        uint32_t stg = (uint32_t)((c & 1) * S_STG * 4);
        gemm_chunk_ldsm(aBase + stg, bBase + stg, acc);
        if (c + 1 < nc)
            gemm_store(sm + ((c + 1) & 1) * S_STG, tid, p);
        __syncthreads();
    }
}

// ---------------- kernel 2: qkv GEMM + fp16 scatter ----------------
__global__ __launch_bounds__(256) void qkv_gemm_tc(const float* __restrict__ x,
                                                   const float* __restrict__ W) {
    extern __shared__ __align__(16) uint32_t sm[];
    int tid = threadIdx.x;
    int wid = tid >> 5, lane = tid & 31;
    int g = lane >> 2, t = lane & 3;
    int wm = wid & 3, wn = wid >> 2;
    int m0 = blockIdx.y * 128;
    int n0 = blockIdx.x * 64;

    float acc[2][4][4] = {};
    gemm_main(x, W, kD, kN, m0, n0, sm, tid, wm, wn, lane, acc, kD);

    __half* qh = (__half*)g_qhV;
    __half* vt = (__half*)g_vtV;
#pragma unroll
    for (int i = 0; i < 2; i++) {
        int mr0 = m0 + wm * 32 + i * 16 + g;
#pragma unroll
        for (int half = 0; half < 2; half++) {
            int m = mr0 + half * 8;
            int b = m >> 11, tt = m & 2047;
#pragma unroll
            for (int nt = 0; nt < 4; nt++) {
#pragma unroll
                for (int e = 0; e < 2; e++) {
                    int n = n0 + wn * 32 + nt * 8 + 2 * t + e;
                    int d = n >> 4, r = n & 15;
                    size_t bh = (size_t)b * kH + (r & 7);
                    __half hv = __float2half(acc[i][nt][half * 2 + e]);
                    if (r < 8) qh[(bh * kT + tt) * kHD + d] = hv;
                    else       vt[(bh * kHD + d) * kT + tt] = hv;
                }
            }
        }
    }
}

// ---------------- kernel 3: qsq partials (reads fp16 q) ----------------
__global__ __launch_bounds__(256) void qsq_part_kernel() {
    int bh = blockIdx.y;
    int t0 = blockIdx.x * 128;
    int tid = threadIdx.x;
    int r = tid >> 1, part = tid & 1;
    const uint4* p4 = g_qhV + ((size_t)bh * kT + t0 + r) * 8 + part * 4;
    float s = 0.f;
#pragma unroll
    for (int i = 0; i < 4; i++) {
        uint4 u = p4[i];
        uint32_t w[4] = {u.x, u.y, u.z, u.w};
#pragma unroll
        for (int j = 0; j < 4; j++) {
            float2 f = __half22float2(*(__half2*)&w[j]);
            s += f.x * f.x + f.y * f.y;
        }
    }
    float rsum = s + __shfl_xor_sync(0xffffffffu, s, 1);
    if (part == 0) g_qsq[(size_t)bh * kT + t0 + r] = rsum;
    __shared__ float sm[256];
    sm[tid] = s;
    __syncthreads();
    for (int w = 128; w > 0; w >>= 1) {
        if (tid < w) sm[tid] += sm[tid + w];
        __syncthreads();
    }
    if (tid == 0) g_part[bh * 16 + blockIdx.x] = sm[0];
}

// ---------------- kernel 4: fp16 attention (R14 proven) ----------------
static constexpr int A_KS = 0;
static constexpr int A_VT = 64 * 36;           // 2304
static constexpr int A_CS = 2 * 64 * 36;       // 4608

__global__ __launch_bounds__(256, 2) void attn_mma_kernel() {
    __shared__ __align__(16) uint32_t sm[2 * 64 * 36 + 64];
    uint32_t* KsU = sm + A_KS;
    uint32_t* VtU = sm + A_VT;
    float*    csK = (float*)(sm + A_CS);

    int tid  = threadIdx.x;
    int wid  = tid >> 5;
    int lane = tid & 31;
    int g    = lane >> 2;
    int t    = lane & 3;

    int tq0 = blockIdx.x * 128;
    int h = blockIdx.y, b = blockIdx.z;
    int bh = b * kH + h;
    const uint32_t* qhu = (const uint32_t*)g_qhV + (size_t)bh * kT * 32;
    const uint4*    kv4 = g_qhV + (size_t)bh * kT * 8;
    const uint4*    vt4 = g_vtV + (size_t)bh * kHD * 256;
    const float*    qsqp = g_qsq + (size_t)bh * kT;

    float asum = 0.f;
#pragma unroll
    for (int i = 0; i < 16; i++) asum += g_part[bh * 16 + i];
    float bmax = sqrtf(__uint_as_float(g_bmax_bits[b]));
    float cc  = ALPHA / (sqrtf(asum) * bmax + EPSV);
    float cc2 = 2.f * cc;

    int r0 = wid * 16 + g;

    uint32_t qa[4][4];
    {
        const uint32_t* q0 = qhu + (size_t)(tq0 + r0) * 32;
        const uint32_t* q1 = q0 + 8 * 32;
#pragma unroll
        for (int kc = 0; kc < 4; kc++) {
            qa[kc][0] = q0[kc * 8 + t];
            qa[kc][1] = q1[kc * 8 + t];
            qa[kc][2] = q0[kc * 8 + t + 4];
            qa[kc][3] = q1[kc * 8 + t + 4];
        }
    }
    float cqq0 = cc * qsqp[tq0 + r0];
    float cqq1 = cc * qsqp[tq0 + r0 + 8];

    int lq8 = lane >> 3, lrw = lane & 7;
    uint32_t lrow = (uint32_t)(8 * (lq8 >> 1) + lrw);
    uint32_t lcol = (uint32_t)((lq8 & 1) * 4);
    uint32_t ksBase = (uint32_t)__cvta_generic_to_shared(KsU) + (lrow * 36 + lcol) * 4;
    uint32_t vtBase = (uint32_t)__cvta_generic_to_shared(VtU) + (lrow * 36 + lcol) * 4;

    float o[8][4] = {};
    float rs0 = 0.f, rs1 = 0.f;

    int lr = tid >> 2;
    int lqr = tid & 3;

    for (int it = 0; it < 32; it++) {
        int s0 = it * 64;
        {
            const uint4* ksrc = kv4 + (size_t)(s0 + lr) * 8 + lqr * 2;
            uint4 k0 = ksrc[0], k1 = ksrc[1];
            *(uint4*)&KsU[lr * 36 + lqr * 8]     = k0;
            *(uint4*)&KsU[lr * 36 + lqr * 8 + 4] = k1;
            const uint4* vsrc = vt4 + (size_t)lr * 256 + s0 / 8 + lqr * 2;
            uint4 v0 = vsrc[0], v1 = vsrc[1];
            *(uint4*)&VtU[lr * 36 + lqr * 8]     = v0;
            *(uint4*)&VtU[lr * 36 + lqr * 8 + 4] = v1;
            if (tid < 64) csK[tid] = cc * qsqp[s0 + tid];
        }
        __syncthreads();

        float sacc[8][4] = {};
#pragma unroll
        for (int kc = 0; kc < 4; kc++) {
            uint32_t kaddr = ksBase + (uint32_t)(kc * 32);
#pragma unroll
            for (int np = 0; np < 4; np++) {
                uint32_t b0a, b1a, b0b, b1b;
                ldsm4(b0a, b1a, b0b, b1b, kaddr + (uint32_t)(np * 2304));
                mma16h(sacc[2 * np],     qa[kc][0], qa[kc][1], qa[kc][2], qa[kc][3], b0a, b1a);
                mma16h(sacc[2 * np + 1], qa[kc][0], qa[kc][1], qa[kc][2], qa[kc][3], b0b, b1b);
            }
        }

        uint32_t pa[8][2];
#pragma unroll
        for (int n = 0; n < 8; n++) {
            int j0 = n * 8 + 2 * t;
            float k0 = csK[j0], k1 = csK[j0 + 1];
            float e0 = __expf(fmaf(cc2, sacc[n][0], -(cqq0 + k0)));
            float e1 = __expf(fmaf(cc2, sacc[n][1], -(cqq0 + k1)));
            float e2 = __expf(fmaf(cc2, sacc[n][2], -(cqq1 + k0)));
            float e3 = __expf(fmaf(cc2, sacc[n][3], -(cqq1 + k1)));
            rs0 += e0 + e1;
            rs1 += e2 + e3;
            pa[n][0] = pack_f16(e0, e1);
            pa[n][1] = pack_f16(e2, e3);
        }

#pragma unroll
        for (int kc = 0; kc < 4; kc++) {
            uint32_t a0 = pa[2 * kc][0];
            uint32_t a1 = pa[2 * kc][1];
            uint32_t a2 = pa[2 * kc + 1][0];
            uint32_t a3 = pa[2 * kc + 1][1];
            uint32_t vaddr = vtBase + (uint32_t)(kc * 32);
#pragma unroll
            for (int np = 0; np < 4; np++) {
                uint32_t b0a, b1a, b0b, b1b;
                ldsm4(b0a, b1a, b0b, b1b, vaddr + (uint32_t)(np * 2304));
                mma16h(o[2 * np],     a0, a1, a2, a3, b0a, b1a);
                mma16h(o[2 * np + 1], a0, a1, a2, a3, b0b, b1b);
            }
        }
        __syncthreads();
    }

    rs0 += __shfl_xor_sync(0xffffffffu, rs0, 1);
    rs0 += __shfl_xor_sync(0xffffffffu, rs0, 2);
    rs1 += __shfl_xor_sync(0xffffffffu, rs1, 1);
    rs1 += __shfl_xor_sync(0xffffffffu, rs1, 2);
    float inv0 = 1.f / rs0;
    float inv1 = 1.f / rs1;

    size_t ro0 = ((size_t)b * kT + tq0 + r0) * kD + h * kHD;
    size_t ro1 = ro0 + (size_t)8 * kD;
#pragma unroll
    for (int n = 0; n < 8; n++) {
        int j0 = n * 8 + 2 * t;
        float2 w0 = make_float2(o[n][0] * inv0, o[n][1] * inv0);
        float2 w1 = make_float2(o[n][2] * inv1, o[n][3] * inv1);
        *(float2*)&g_o[ro0 + j0] = w0;
        *(float2*)&g_o[ro1 + j0] = w1;
    }
}

// ---------------- kernel 5: proj GEMM + bias ----------------
__global__ __launch_bounds__(256) void proj_gemm_tc(const float* __restrict__ W,
                                                    const float* __restrict__ bias,
                                                    float* __restrict__ out) {
    extern __shared__ __align__(16) uint32_t sm[];
    int tid = threadIdx.x;
    int wid = tid >> 5, lane = tid & 31;
    int g = lane >> 2, t = lane & 3;
    int wm = wid & 3, wn = wid >> 2;
    int m0 = blockIdx.y * 128;
    int n0 = blockIdx.x * 64;

    float acc[2][4][4] = {};
    gemm_main(g_o, W, kD, kD, m0, n0, sm, tid, wm, wn, lane, acc, kD);
#pragma unroll
    for (int i = 0; i < 2; i++) {
        int mr0 = m0 + wm * 32 + i * 16 + g;
#pragma unroll
        for (int nt = 0; nt < 4; nt++) {
            int n = n0 + wn * 32 + nt * 8 + 2 * t;
            float2 bb = *(const float2*)&bias[n];
            float2 w0 = make_float2(acc[i][nt][0] + bb.x, acc[i][nt][1] + bb.y);
            float2 w1 = make_float2(acc[i][nt][2] + bb.x, acc[i][nt][3] + bb.y);
            *(float2*)&out[(size_t)mr0 * kD + n]       = w0;
            *(float2*)&out[(size_t)(mr0 + 8) * kD + n] = w1;
        }
    }
}

// ---------------- launch ----------------
extern "C" void kernel_launch(void* const* d_in, const int* in_sizes, int n_in,
                              void* d_out, int out_size) {
    (void)in_sizes; (void)n_in; (void)out_size;
    const float* x     = (const float*)d_in[0];
    const float* Wqkv  = (const float*)d_in[1];
    const float* Wproj = (const float*)d_in[2];
    const float* bproj = (const float*)d_in[3];
    float* out = (float*)d_out;

    cudaFuncSetAttribute(qkv_gemm_tc, cudaFuncAttributeMaxDynamicSharedMemorySize,
                         kGemmSmem);
    cudaFuncSetAttribute(proj_gemm_tc, cudaFuncAttributeMaxDynamicSharedMemorySize,
                         kGemmSmem);

    bmax_kernel<<<dim3(kT / 64, kB), 256>>>(x);
    noop_kernel<<<1, 32>>>();
    noop_kernel<<<1, 32>>>();
    qkv_gemm_tc<<<dim3(kN / 64, (kB * kT) / 128), 256, kGemmSmem>>>(x, Wqkv);  // 4th: profiled
    qsq_part_kernel<<<dim3(kT / 128, kB * kH), 256>>>();
    attn_mma_kernel<<<dim3(kT / 128, kH, kB), 256>>>();
    proj_gemm_tc<<<dim3(kD / 64, (kB * kT) / 128), 256, kGemmSmem>>>(Wproj, bproj, out);
}